// round 15
// baseline (speedup 1.0000x reference)
#include <cuda_runtime.h>
#include <float.h>

#define NPROP 1024
#define NC    81
#define NCLS  80
#define FD    1024
#define KTOP  100
#define CAP   (NCLS * KTOP)
#define NBLK  80
#define NT    512
#define SELCAP 4096

#define SCORE_TH 0.05f
#define NMS_TH   0.5f
#define BBOX_CLIP 4.135166556742356f
#define IMG_W_M1 1215.0f
#define IMG_H_M1 799.0f

// output layout (floats): boxes[100*4] | scores[100] | feats[100*1024] | labels[100]
#define OFF_S 400
#define OFF_F 500
#define OFF_L 102900

// ---------------- device scratch ------------
__device__ int    g_ccnt[NCLS];                     // zeroed at end of each run
__device__ unsigned long long g_cand[NCLS * NPROP]; // packed (score, propidx)
__device__ float4 g_dec4[NCLS * NPROP];             // decoded boxes
__device__ int    g_hist[256];
__device__ int    g_count;
__device__ unsigned long long g_ckey[CAP];
__device__ float4 g_cbox4[CAP];
__device__ int    g_corig[CAP];

// ---------------- inter-block barrier (self-resetting, replay-safe) ---------
__device__ unsigned g_ctr = 0;
__device__ volatile unsigned g_rel;

__device__ __forceinline__ void gbar() {
    __threadfence();
    __syncthreads();
    if (threadIdx.x == 0) {
        unsigned e = g_rel;
        if (atomicAdd(&g_ctr, 1u) == NBLK - 1u) {
            g_ctr = 0u;
            __threadfence();
            atomicAdd((unsigned*)&g_rel, 1u);
        } else {
            while (g_rel == e) { }
        }
    }
    __syncthreads();
}

__device__ __forceinline__ unsigned long long tk_key(float s, unsigned flat) {
    return (((unsigned long long)__float_as_uint(s)) << 32) |
           (unsigned long long)(0xFFFFFFFFu - flat);
}

__device__ __forceinline__ void decode_store(
        const float* __restrict__ reg, const float* __restrict__ props,
        int n, int c, float prob) {
    float x1 = props[n * 4 + 0];
    float y1 = props[n * 4 + 1];
    float x2 = props[n * 4 + 2];
    float y2 = props[n * 4 + 3];
    float bw = x2 - x1 + 1.0f;
    float bh = y2 - y1 + 1.0f;
    float cx = x1 + 0.5f * bw;
    float cy = y1 + 0.5f * bh;

    const float* r = reg + n * NC * 4 + c * 4;
    float dx = r[0] / 10.0f;
    float dy = r[1] / 10.0f;
    float dw = fminf(r[2] / 5.0f, BBOX_CLIP);
    float dh = fminf(r[3] / 5.0f, BBOX_CLIP);

    float pcx = dx * bw + cx;
    float pcy = dy * bh + cy;
    float pw  = expf(dw) * bw;
    float ph  = expf(dh) * bh;

    float bx1 = fminf(fmaxf(pcx - 0.5f * pw, 0.0f), IMG_W_M1);
    float by1 = fminf(fmaxf(pcy - 0.5f * ph, 0.0f), IMG_H_M1);
    float bx2 = fminf(fmaxf(pcx + 0.5f * pw - 1.0f, 0.0f), IMG_W_M1);
    float by2 = fminf(fmaxf(pcy + 0.5f * ph - 1.0f, 0.0f), IMG_H_M1);

    g_dec4[(c - 1) * NPROP + n] = make_float4(bx1, by1, bx2, by2);
    int slot = atomicAdd(&g_ccnt[c - 1], 1);
    g_cand[(c - 1) * NPROP + slot] = tk_key(prob, (unsigned)n);
}

// smem layout (words):
//  cand u64[1024]            [0,2048)
//  skey f32[1024]            [2048,3072)
//  sorig i32[1024]           [3072,4096)
//  sbox4 float4[1024]        [4096,8192)
//  sarea f32[1024]           [8192,9216)
//  mask  u32[1024*32]        [9216,41984)
//  s_rem u32[32]             [41984,42016)
//  s_sup u32[32]             [42016,42048)
//  s_cer u32[32]             [42048,42080)
#define SMEM_WORDS 42080
#define SMEM_BYTES (SMEM_WORDS * 4)

__global__ void __launch_bounds__(NT, 1) kMain(
        const float* __restrict__ logits,
        const float* __restrict__ reg,
        const float* __restrict__ props,
        const float* __restrict__ feats,
        float* __restrict__ out) {
    extern __shared__ unsigned sm[];
    int t = threadIdx.x;
    int b = blockIdx.x;
    int wid = t >> 5, l = t & 31;

    if (b == NBLK - 1 && t == 0) g_count = 0;
    if (b == NBLK - 2 && t < 256) g_hist[t] = 0;

    // ===== Phase A: softmax + sparse decode, one proposal per warp ==========
    {
        int n = b * 16 + wid;            // 80*16=1280 warps; first 1024 active
        if (n < NPROP) {
            const float* lg = logits + n * NC;
            float v0 = lg[l];
            float v1 = lg[l + 32];
            float v2 = (l < 17) ? lg[l + 64] : -FLT_MAX;

            float m = fmaxf(fmaxf(v0, v1), v2);
            #pragma unroll
            for (int off = 16; off; off >>= 1)
                m = fmaxf(m, __shfl_xor_sync(0xffffffffu, m, off));

            float e0 = expf(v0 - m);
            float e1 = expf(v1 - m);
            float e2 = (l < 17) ? expf(v2 - m) : 0.0f;
            float s = e0 + e1 + e2;
            #pragma unroll
            for (int off = 16; off; off >>= 1)
                s += __shfl_xor_sync(0xffffffffu, s, off);
            float inv = 1.0f / s;

            float pr[3] = { e0 * inv, e1 * inv, e2 * inv };
            int   cc[3] = { l, l + 32, l + 64 };
            #pragma unroll
            for (int q = 0; q < 3; q++) {
                int c = cc[q];
                if (c >= 1 && c < NC && pr[q] > SCORE_TH)
                    decode_store(reg, props, n, c, pr[q]);
            }
        }
    }

    gbar();

    // ================= Phase B: per-class NMS (class = blockIdx) ============
    {
        unsigned long long* cand = (unsigned long long*)sm;
        float*    skey   = (float*)(sm + 2048);
        int*      sorig  = (int*)(sm + 3072);
        float4*   sbox4  = (float4*)(sm + 4096);
        float*    sarea  = (float*)(sm + 8192);
        unsigned* mask   = sm + 9216;
        unsigned* s_rem  = sm + 41984;
        unsigned* s_sup  = sm + 42016;
        unsigned* s_cer  = sm + 42048;
        __shared__ int s_base;

        int c = b;
        int nv = g_ccnt[c];

        for (int i = t; i < nv; i += NT) cand[i] = g_cand[c * NPROP + i];
        if (t < 32) { s_sup[t] = 0u; s_cer[t] = 0u; }
        __syncthreads();

        if (nv > 0) {
            int nwords = (nv + 31) >> 5;

            // rank-sort via packed u64 key (score desc, orig idx asc)
            for (int ii = t; ii < nv; ii += NT) {
                unsigned long long mk = cand[ii];
                int r = 0;
                for (int j = 0; j < nv; j++) r += (cand[j] > mk);
                float sc = __uint_as_float((unsigned)(mk >> 32));
                int mi = (int)(0xFFFFFFFFu - (unsigned)mk);
                skey[r]  = sc;
                sorig[r] = mi;
                float4 bx = g_dec4[c * NPROP + mi];
                sbox4[r] = bx;
                sarea[r] = (bx.z - bx.x + 1.0f) * (bx.w - bx.y + 1.0f);
            }
            __syncthreads();

            // IoU suppression bitmask, cell-parallel with triangle skip
            int cells = nv * nwords;
            for (int cell = t; cell < cells; cell += NT) {
                int i = cell / nwords;
                int w = cell - i * nwords;
                int jbase = w << 5;
                int iw5 = i >> 5;
                unsigned mword = 0;
                if (w >= iw5) {                         // words strictly below diag are 0
                    float4 bi = sbox4[i];
                    float ai = sarea[i];
                    int jend = min(32, nv - jbase);
                    if (w > iw5) {
                        // fully above diagonal: no j>i test needed
                        for (int bb = 0; bb < jend; bb++) {
                            int j = jbase + bb;
                            float4 bj = sbox4[j];
                            float xx1 = fmaxf(bi.x, bj.x);
                            float yy1 = fmaxf(bi.y, bj.y);
                            float xx2 = fminf(bi.z, bj.z);
                            float yy2 = fminf(bi.w, bj.w);
                            float iw = fmaxf(xx2 - xx1 + 1.0f, 0.0f);
                            float ih = fmaxf(yy2 - yy1 + 1.0f, 0.0f);
                            float inter = iw * ih;
                            float iou = inter / (ai + sarea[j] - inter);
                            if (iou > NMS_TH) mword |= (1u << bb);
                        }
                    } else {
                        // diagonal word: per-bit j>i test
                        for (int bb = (i & 31) + 1; bb < jend; bb++) {
                            int j = jbase + bb;
                            float4 bj = sbox4[j];
                            float xx1 = fmaxf(bi.x, bj.x);
                            float yy1 = fmaxf(bi.y, bj.y);
                            float xx2 = fminf(bi.z, bj.z);
                            float yy2 = fminf(bi.w, bj.w);
                            float iw = fmaxf(xx2 - xx1 + 1.0f, 0.0f);
                            float ih = fmaxf(yy2 - yy1 + 1.0f, 0.0f);
                            float inter = iw * ih;
                            float iou = inter / (ai + sarea[j] - inter);
                            if (iou > NMS_TH) mword |= (1u << bb);
                        }
                    }
                }
                mask[(i << 5) + w] = mword;
                if (mword) atomicOr(&s_sup[w], mword);
            }
            __syncthreads();

            // rows of certainly-kept boxes -> s_cer (parallel OR)
            for (int cell = t; cell < cells; cell += NT) {
                int i = cell / nwords;
                int w = cell - i * nwords;
                if (w < (i >> 5)) continue;             // zero words
                bool certain = !((s_sup[i >> 5] >> (i & 31)) & 1u);
                if (certain) {
                    unsigned mword = mask[(i << 5) + w];
                    if (mword) atomicOr(&s_cer[w], mword);
                }
            }
            __syncthreads();

            // warp 0: short serial walk over uncertain boxes only
            if (t < 32) {
                unsigned rem = (t < nwords) ? s_cer[t] : 0u;
                for (int wi = 0; wi < nwords; wi++) {
                    int rembits = nv - (wi << 5);
                    unsigned validm = (rembits >= 32) ? 0xffffffffu : ((1u << rembits) - 1u);
                    unsigned remw = __shfl_sync(0xffffffffu, rem, wi);
                    unsigned alive = s_sup[wi] & validm & ~remw;
                    while (alive) {
                        int bb = __ffs(alive) - 1;
                        int j = (wi << 5) + bb;
                        unsigned row = (t < nwords) ? mask[(j << 5) + t] : 0u;
                        rem |= row;
                        alive &= ~(1u << bb);
                        alive &= ~__shfl_sync(0xffffffffu, row, wi);
                    }
                }
                s_rem[t] = (t < nwords) ? rem : 0u;
            }
            __syncthreads();

            // one base atomic per class
            if (t == 0) {
                int tot = 0;
                for (int w = 0; w < nwords; w++) {
                    int rembits = nv - (w << 5);
                    unsigned validm = (rembits >= 32) ? 0xffffffffu : ((1u << rembits) - 1u);
                    tot += __popc((~s_rem[w]) & validm);
                }
                if (tot > KTOP) tot = KTOP;
                s_base = atomicAdd(&g_count, tot);
            }
            __syncthreads();
            int base = s_base;

            // compact survivors (first KTOP per class)
            for (int i = t; i < nv; i += NT) {
                unsigned rw = s_rem[i >> 5];
                if (!((rw >> (i & 31)) & 1)) {
                    int kr = 0;
                    for (int w = 0; w < (i >> 5); w++) kr += __popc(~s_rem[w]);
                    kr += __popc((~rw) & ((1u << (i & 31)) - 1u));
                    if (kr < KTOP) {
                        int p = base + kr;
                        float sc = skey[i];
                        g_ckey[p]  = tk_key(sc, (unsigned)(c * NPROP + i));
                        g_cbox4[p] = sbox4[i];
                        g_corig[p] = sorig[i];
                        int bb = (int)(sc * 256.0f);
                        bb = max(0, min(bb, 255));
                        atomicAdd(&g_hist[bb], 1);
                    }
                }
            }
        }
    }

    gbar();

    // ================= Phase C: distributed top-K + outputs + gather ========
    {
        int* ssuf = (int*)sm;                                   // [0,256)
        unsigned long long* skeys = (unsigned long long*)(sm + 512);
        int* sgid = (int*)(sm + 512 + 2 * SELCAP);
        __shared__ int sc_cnt, sc_cut;
        __shared__ int s_nw;
        __shared__ int w_r[128], w_gi[128];

        int M = g_count;
        if (M > CAP) M = CAP;
        int Kfound = (M < KTOP) ? M : KTOP;

        if (t == 0) { sc_cnt = 0; s_nw = 0; }

        // warp 0: suffix sums of 256-bin histogram via shuffles
        if (t < 32) {
            int h[8];
            #pragma unroll
            for (int q = 0; q < 8; q++) h[q] = g_hist[t * 8 + q];
            int run = 0;
            int lsuf[8];
            #pragma unroll
            for (int q = 7; q >= 0; q--) { run += h[q]; lsuf[q] = run; }
            int inc = run;
            #pragma unroll
            for (int off = 1; off < 32; off <<= 1) {
                int o = __shfl_down_sync(0xffffffffu, inc, off);
                if (t + off < 32) inc += o;
            }
            int above = inc - run;
            #pragma unroll
            for (int q = 0; q < 8; q++) ssuf[t * 8 + q] = lsuf[q] + above;
        }
        __syncthreads();
        if (M > 0 && t < 256) {
            if (ssuf[t] >= Kfound && (t == 255 || ssuf[t + 1] < Kfound)) sc_cut = t;
        }
        __syncthreads();

        if (M > 0) {
            int cut = sc_cut;

            // compact candidates above cut (same set in every block)
            for (int i = t; i < M; i += NT) {
                unsigned long long key = g_ckey[i];
                float sc = __uint_as_float((unsigned)(key >> 32));
                int bb = (int)(sc * 256.0f);
                bb = max(0, min(bb, 255));
                if (bb >= cut) {
                    int p = atomicAdd(&sc_cnt, 1);
                    if (p < SELCAP) { skeys[p] = key; sgid[p] = i; }
                }
            }
            __syncthreads();
            int Msel = sc_cnt;
            if (Msel > SELCAP) Msel = SELCAP;

            // rank candidates owned by this block
            for (int ii = t; ii < Msel; ii += NT) {
                int gi = sgid[ii];
                if (gi % NBLK != b) continue;
                unsigned long long mk = skeys[ii];
                int r = 0;
                for (int j = 0; j < Msel; j++) r += (skeys[j] > mk);
                if (r < KTOP) {
                    int p = atomicAdd(&s_nw, 1);
                    w_r[p]  = r;
                    w_gi[p] = gi;
                }
            }
            __syncthreads();

            // write winners (meta + feature gather; rows are 256 x float4)
            int nw = s_nw;
            for (int e0 = 0; e0 < nw; e0 += 2) {
                int e  = e0 + (t >> 8);
                int tt = t & 255;
                if (e < nw) {
                    int r  = w_r[e];
                    int gi = w_gi[e];
                    if (tt == 0) {
                        unsigned long long key = g_ckey[gi];
                        float sc = __uint_as_float((unsigned)(key >> 32));
                        unsigned flat = 0xFFFFFFFFu - (unsigned)(key & 0xFFFFFFFFu);
                        ((float4*)out)[r] = g_cbox4[gi];
                        out[OFF_S + r] = sc;
                        out[OFF_L + r] = (float)(flat / NPROP + 1);
                    }
                    int orig = g_corig[gi];
                    const float4* src = (const float4*)(feats + (size_t)orig * FD);
                    float4* dst = (float4*)(out + OFF_F + (size_t)r * FD);
                    dst[tt] = src[tt];
                }
            }
        }

        // zero-fill unfilled slots [Kfound, KTOP)
        for (int k = Kfound + b; k < KTOP; k += NBLK) {
            if (t == 0) {
                ((float4*)out)[k] = make_float4(0.0f, 0.0f, 0.0f, 0.0f);
                out[OFF_S + k] = 0.0f;
                out[OFF_L + k] = 0.0f;
            }
            if (t < 256) {
                float4* dst = (float4*)(out + OFF_F + (size_t)k * FD);
                dst[t] = make_float4(0.0f, 0.0f, 0.0f, 0.0f);
            }
        }

        // reset per-class counters for next replay
        if (b == 0 && t < NCLS) g_ccnt[t] = 0;
    }
}

// ---------------- launch -----------------------------------------------------
extern "C" void kernel_launch(void* const* d_in, const int* in_sizes, int n_in,
                              void* d_out, int out_size) {
    const float* logits = (const float*)d_in[0];
    const float* reg    = (const float*)d_in[1];
    const float* props  = (const float*)d_in[2];
    const float* feats  = (const float*)d_in[3];
    float* out = (float*)d_out;

    static bool attr_done = false;
    if (!attr_done) {
        cudaFuncSetAttribute(kMain, cudaFuncAttributeMaxDynamicSharedMemorySize,
                             SMEM_BYTES);
        attr_done = true;
    }

    kMain<<<NBLK, NT, SMEM_BYTES>>>(logits, reg, props, feats, out);
}

// round 17
// speedup vs baseline: 1.1516x; 1.1516x over previous
#include <cuda_runtime.h>
#include <float.h>

#define NPROP 1024
#define NC    81
#define NCLS  80
#define FD    1024
#define KTOP  100
#define CAP   (NCLS * KTOP)
#define NBLK  80
#define NT    256
#define SELCAP 4096

#define SCORE_TH 0.05f
#define NMS_TH   0.5f
#define BBOX_CLIP 4.135166556742356f
#define IMG_W_M1 1215.0f
#define IMG_H_M1 799.0f

// output layout (floats): boxes[100*4] | scores[100] | feats[100*1024] | labels[100]
#define OFF_S 400
#define OFF_F 500
#define OFF_L 102900

// ---------------- device scratch ------------
__device__ int    g_ccnt[NCLS];                     // zeroed at end of each run
__device__ unsigned long long g_cand[NCLS * NPROP]; // packed (score, propidx)
__device__ float4 g_dec4[NCLS * NPROP];             // decoded boxes
__device__ int    g_hist[256];
__device__ int    g_count;
__device__ unsigned long long g_ckey[CAP];
__device__ float4 g_cbox4[CAP];
__device__ int    g_corig[CAP];

// ---------------- inter-block barrier (self-resetting, replay-safe) ---------
__device__ unsigned g_ctr = 0;
__device__ volatile unsigned g_rel;

__device__ __forceinline__ void gbar() {
    __threadfence();
    __syncthreads();
    if (threadIdx.x == 0) {
        unsigned e = g_rel;
        if (atomicAdd(&g_ctr, 1u) == NBLK - 1u) {
            g_ctr = 0u;
            __threadfence();
            atomicAdd((unsigned*)&g_rel, 1u);
        } else {
            while (g_rel == e) { }
        }
    }
    __syncthreads();
}

__device__ __forceinline__ unsigned long long tk_key(float s, unsigned flat) {
    return (((unsigned long long)__float_as_uint(s)) << 32) |
           (unsigned long long)(0xFFFFFFFFu - flat);
}

__device__ __forceinline__ void decode_store(
        const float* __restrict__ reg, const float* __restrict__ props,
        int n, int c, float prob) {
    float x1 = props[n * 4 + 0];
    float y1 = props[n * 4 + 1];
    float x2 = props[n * 4 + 2];
    float y2 = props[n * 4 + 3];
    float bw = x2 - x1 + 1.0f;
    float bh = y2 - y1 + 1.0f;
    float cx = x1 + 0.5f * bw;
    float cy = y1 + 0.5f * bh;

    const float* r = reg + n * NC * 4 + c * 4;
    float dx = r[0] / 10.0f;
    float dy = r[1] / 10.0f;
    float dw = fminf(r[2] / 5.0f, BBOX_CLIP);
    float dh = fminf(r[3] / 5.0f, BBOX_CLIP);

    float pcx = dx * bw + cx;
    float pcy = dy * bh + cy;
    float pw  = expf(dw) * bw;
    float ph  = expf(dh) * bh;

    float bx1 = fminf(fmaxf(pcx - 0.5f * pw, 0.0f), IMG_W_M1);
    float by1 = fminf(fmaxf(pcy - 0.5f * ph, 0.0f), IMG_H_M1);
    float bx2 = fminf(fmaxf(pcx + 0.5f * pw - 1.0f, 0.0f), IMG_W_M1);
    float by2 = fminf(fmaxf(pcy + 0.5f * ph - 1.0f, 0.0f), IMG_H_M1);

    g_dec4[(c - 1) * NPROP + n] = make_float4(bx1, by1, bx2, by2);
    int slot = atomicAdd(&g_ccnt[c - 1], 1);
    g_cand[(c - 1) * NPROP + slot] = tk_key(prob, (unsigned)n);
}

// smem layout (words):
//  cand u64[1024]            [0,2048)
//  skey f32[1024]            [2048,3072)
//  sorig i32[1024]           [3072,4096)
//  sbox4 float4[1024]        [4096,8192)
//  sarea f32[1024]           [8192,9216)
//  mask  u32[1024*32]        [9216,41984)
//  s_rem u32[32]             [41984,42016)
//  s_sup u32[32]             [42016,42048)
//  s_cer u32[32]             [42048,42080)
#define SMEM_WORDS 42080
#define SMEM_BYTES (SMEM_WORDS * 4)

__global__ void __launch_bounds__(NT, 1) kMain(
        const float* __restrict__ logits,
        const float* __restrict__ reg,
        const float* __restrict__ props,
        const float* __restrict__ feats,
        float* __restrict__ out) {
    extern __shared__ unsigned sm[];
    int t = threadIdx.x;
    int b = blockIdx.x;
    int wid = t >> 5, l = t & 31;

    if (b == NBLK - 1 && t == 0) g_count = 0;
    if (b == NBLK - 2 && t < 256) g_hist[t] = 0;

    // ===== Phase A: softmax + sparse decode, 2 proposals per warp via ILP ====
    {
        int gw = b * 8 + wid;            // 640 warps; first 512 take pairs
        if (gw < 512) {
            int n0 = 2 * gw, n1 = n0 + 1;
            const float* lgA = logits + n0 * NC;
            const float* lgB = logits + n1 * NC;
            float a0 = lgA[l], a1 = lgA[l + 32];
            float b0 = lgB[l], b1 = lgB[l + 32];
            float a2 = (l < 17) ? lgA[l + 64] : -FLT_MAX;
            float b2 = (l < 17) ? lgB[l + 64] : -FLT_MAX;

            float mA = fmaxf(fmaxf(a0, a1), a2);
            float mB = fmaxf(fmaxf(b0, b1), b2);
            #pragma unroll
            for (int off = 16; off; off >>= 1) {
                mA = fmaxf(mA, __shfl_xor_sync(0xffffffffu, mA, off));
                mB = fmaxf(mB, __shfl_xor_sync(0xffffffffu, mB, off));
            }

            float eA0 = expf(a0 - mA), eA1 = expf(a1 - mA);
            float eB0 = expf(b0 - mB), eB1 = expf(b1 - mB);
            float eA2 = (l < 17) ? expf(a2 - mA) : 0.0f;
            float eB2 = (l < 17) ? expf(b2 - mB) : 0.0f;
            float sA = eA0 + eA1 + eA2;
            float sB = eB0 + eB1 + eB2;
            #pragma unroll
            for (int off = 16; off; off >>= 1) {
                sA += __shfl_xor_sync(0xffffffffu, sA, off);
                sB += __shfl_xor_sync(0xffffffffu, sB, off);
            }
            float invA = 1.0f / sA, invB = 1.0f / sB;

            float prA[3] = { eA0 * invA, eA1 * invA, eA2 * invA };
            float prB[3] = { eB0 * invB, eB1 * invB, eB2 * invB };
            int   cc[3]  = { l, l + 32, l + 64 };
            #pragma unroll
            for (int q = 0; q < 3; q++) {
                int c = cc[q];
                if (c >= 1 && c < NC) {
                    if (prA[q] > SCORE_TH) decode_store(reg, props, n0, c, prA[q]);
                    if (prB[q] > SCORE_TH) decode_store(reg, props, n1, c, prB[q]);
                }
            }
        }
    }

    gbar();

    // ================= Phase B: per-class NMS (class = blockIdx) ============
    {
        unsigned long long* cand = (unsigned long long*)sm;
        float*    skey   = (float*)(sm + 2048);
        int*      sorig  = (int*)(sm + 3072);
        float4*   sbox4  = (float4*)(sm + 4096);
        float*    sarea  = (float*)(sm + 8192);
        unsigned* mask   = sm + 9216;
        unsigned* s_rem  = sm + 41984;
        unsigned* s_sup  = sm + 42016;
        unsigned* s_cer  = sm + 42048;
        __shared__ int s_base;

        int c = b;
        int nv = g_ccnt[c];

        for (int i = t; i < nv; i += NT) cand[i] = g_cand[c * NPROP + i];
        if (t < 32) { s_sup[t] = 0u; s_cer[t] = 0u; }
        __syncthreads();

        if (nv > 0) {
            int nwords = (nv + 31) >> 5;

            // rank-sort via packed u64 key (score desc, orig idx asc)
            for (int ii = t; ii < nv; ii += NT) {
                unsigned long long mk = cand[ii];
                int r = 0;
                for (int j = 0; j < nv; j++) r += (cand[j] > mk);
                float sc = __uint_as_float((unsigned)(mk >> 32));
                int mi = (int)(0xFFFFFFFFu - (unsigned)mk);
                skey[r]  = sc;
                sorig[r] = mi;
                float4 bx = g_dec4[c * NPROP + mi];
                sbox4[r] = bx;
                sarea[r] = (bx.z - bx.x + 1.0f) * (bx.w - bx.y + 1.0f);
            }
            __syncthreads();

            // IoU suppression bitmask, cell-parallel with triangle skip
            int cells = nv * nwords;
            for (int cell = t; cell < cells; cell += NT) {
                int i = cell / nwords;
                int w = cell - i * nwords;
                int iw5 = i >> 5;
                unsigned mword = 0;
                if (w >= iw5) {                        // below-diag words stay 0
                    float4 bi = sbox4[i];
                    float ai = sarea[i];
                    int jbase = w << 5;
                    int jend = min(32, nv - jbase);
                    int bb0 = (w == iw5) ? (i & 31) + 1 : 0;
                    for (int bb = bb0; bb < jend; bb++) {
                        int j = jbase + bb;
                        float4 bj = sbox4[j];
                        float xx1 = fmaxf(bi.x, bj.x);
                        float yy1 = fmaxf(bi.y, bj.y);
                        float xx2 = fminf(bi.z, bj.z);
                        float yy2 = fminf(bi.w, bj.w);
                        float iw = fmaxf(xx2 - xx1 + 1.0f, 0.0f);
                        float ih = fmaxf(yy2 - yy1 + 1.0f, 0.0f);
                        float inter = iw * ih;
                        float iou = inter / (ai + sarea[j] - inter);
                        if (iou > NMS_TH) mword |= (1u << bb);
                    }
                }
                mask[(i << 5) + w] = mword;
                if (mword) atomicOr(&s_sup[w], mword);
            }
            __syncthreads();

            // rows of certainly-kept boxes -> s_cer (parallel OR, skip zero words)
            for (int cell = t; cell < cells; cell += NT) {
                int i = cell / nwords;
                int w = cell - i * nwords;
                if (w < (i >> 5)) continue;
                bool certain = !((s_sup[i >> 5] >> (i & 31)) & 1u);
                if (certain) {
                    unsigned mword = mask[(i << 5) + w];
                    if (mword) atomicOr(&s_cer[w], mword);
                }
            }
            __syncthreads();

            // warp 0: short serial walk over uncertain boxes only
            if (t < 32) {
                unsigned rem = (t < nwords) ? s_cer[t] : 0u;
                for (int wi = 0; wi < nwords; wi++) {
                    int rembits = nv - (wi << 5);
                    unsigned validm = (rembits >= 32) ? 0xffffffffu : ((1u << rembits) - 1u);
                    unsigned remw = __shfl_sync(0xffffffffu, rem, wi);
                    unsigned alive = s_sup[wi] & validm & ~remw;
                    while (alive) {
                        int bb = __ffs(alive) - 1;
                        int j = (wi << 5) + bb;
                        unsigned row = (t < nwords) ? mask[(j << 5) + t] : 0u;
                        rem |= row;
                        alive &= ~(1u << bb);
                        alive &= ~__shfl_sync(0xffffffffu, row, wi);
                    }
                }
                s_rem[t] = (t < nwords) ? rem : 0u;
            }
            __syncthreads();

            // one base atomic per class
            if (t == 0) {
                int tot = 0;
                for (int w = 0; w < nwords; w++) {
                    int rembits = nv - (w << 5);
                    unsigned validm = (rembits >= 32) ? 0xffffffffu : ((1u << rembits) - 1u);
                    tot += __popc((~s_rem[w]) & validm);
                }
                if (tot > KTOP) tot = KTOP;
                s_base = atomicAdd(&g_count, tot);
            }
            __syncthreads();
            int base = s_base;

            // compact survivors (first KTOP per class)
            for (int i = t; i < nv; i += NT) {
                unsigned rw = s_rem[i >> 5];
                if (!((rw >> (i & 31)) & 1)) {
                    int kr = 0;
                    for (int w = 0; w < (i >> 5); w++) kr += __popc(~s_rem[w]);
                    kr += __popc((~rw) & ((1u << (i & 31)) - 1u));
                    if (kr < KTOP) {
                        int p = base + kr;
                        float sc = skey[i];
                        g_ckey[p]  = tk_key(sc, (unsigned)(c * NPROP + i));
                        g_cbox4[p] = sbox4[i];
                        g_corig[p] = sorig[i];
                        int bb = (int)(sc * 256.0f);
                        bb = max(0, min(bb, 255));
                        atomicAdd(&g_hist[bb], 1);
                    }
                }
            }
        }
    }

    gbar();

    // ================= Phase C: distributed top-K + outputs + gather ========
    {
        int* ssuf = (int*)sm;                                   // [0,256)
        unsigned long long* skeys = (unsigned long long*)(sm + 512);
        int* sgid = (int*)(sm + 512 + 2 * SELCAP);
        __shared__ int sc_cnt, sc_cut;
        __shared__ int s_nw;
        __shared__ int w_r[128], w_gi[128];

        int M = g_count;
        if (M > CAP) M = CAP;
        int Kfound = (M < KTOP) ? M : KTOP;

        if (t == 0) { sc_cnt = 0; s_nw = 0; }

        // warp 0: suffix sums of 256-bin histogram via shuffles
        if (t < 32) {
            int h[8];
            #pragma unroll
            for (int q = 0; q < 8; q++) h[q] = g_hist[t * 8 + q];
            int run = 0;
            int lsuf[8];
            #pragma unroll
            for (int q = 7; q >= 0; q--) { run += h[q]; lsuf[q] = run; }
            int inc = run;
            #pragma unroll
            for (int off = 1; off < 32; off <<= 1) {
                int o = __shfl_down_sync(0xffffffffu, inc, off);
                if (t + off < 32) inc += o;
            }
            int above = inc - run;
            #pragma unroll
            for (int q = 0; q < 8; q++) ssuf[t * 8 + q] = lsuf[q] + above;
        }
        __syncthreads();
        if (M > 0 && t < 256) {
            if (ssuf[t] >= Kfound && (t == 255 || ssuf[t + 1] < Kfound)) sc_cut = t;
        }
        __syncthreads();

        if (M > 0) {
            int cut = sc_cut;

            // compact candidates above cut (same set in every block)
            for (int i = t; i < M; i += NT) {
                unsigned long long key = g_ckey[i];
                float sc = __uint_as_float((unsigned)(key >> 32));
                int bb = (int)(sc * 256.0f);
                bb = max(0, min(bb, 255));
                if (bb >= cut) {
                    int p = atomicAdd(&sc_cnt, 1);
                    if (p < SELCAP) { skeys[p] = key; sgid[p] = i; }
                }
            }
            __syncthreads();
            int Msel = sc_cnt;
            if (Msel > SELCAP) Msel = SELCAP;

            // rank candidates owned by this block
            for (int ii = t; ii < Msel; ii += NT) {
                int gi = sgid[ii];
                if (gi % NBLK != b) continue;
                unsigned long long mk = skeys[ii];
                int r = 0;
                for (int j = 0; j < Msel; j++) r += (skeys[j] > mk);
                if (r < KTOP) {
                    int p = atomicAdd(&s_nw, 1);
                    w_r[p]  = r;
                    w_gi[p] = gi;
                }
            }
            __syncthreads();

            // write winners (meta + feature gather)
            int nw = s_nw;
            for (int e = 0; e < nw; e++) {
                int r  = w_r[e];
                int gi = w_gi[e];
                if (t == 0) {
                    unsigned long long key = g_ckey[gi];
                    float sc = __uint_as_float((unsigned)(key >> 32));
                    unsigned flat = 0xFFFFFFFFu - (unsigned)(key & 0xFFFFFFFFu);
                    ((float4*)out)[r] = g_cbox4[gi];
                    out[OFF_S + r] = sc;
                    out[OFF_L + r] = (float)(flat / NPROP + 1);
                }
                int orig = g_corig[gi];
                const float4* src = (const float4*)(feats + (size_t)orig * FD);
                float4* dst = (float4*)(out + OFF_F + (size_t)r * FD);
                dst[t] = src[t];
            }
        }

        // zero-fill unfilled slots [Kfound, KTOP)
        for (int k = Kfound + b; k < KTOP; k += NBLK) {
            if (t == 0) {
                ((float4*)out)[k] = make_float4(0.0f, 0.0f, 0.0f, 0.0f);
                out[OFF_S + k] = 0.0f;
                out[OFF_L + k] = 0.0f;
            }
            float4* dst = (float4*)(out + OFF_F + (size_t)k * FD);
            dst[t] = make_float4(0.0f, 0.0f, 0.0f, 0.0f);
        }

        // reset per-class counters for next replay
        if (b == 0 && t < NCLS) g_ccnt[t] = 0;
    }
}

// ---------------- launch -----------------------------------------------------
extern "C" void kernel_launch(void* const* d_in, const int* in_sizes, int n_in,
                              void* d_out, int out_size) {
    const float* logits = (const float*)d_in[0];
    const float* reg    = (const float*)d_in[1];
    const float* props  = (const float*)d_in[2];
    const float* feats  = (const float*)d_in[3];
    float* out = (float*)d_out;

    static bool attr_done = false;
    if (!attr_done) {
        cudaFuncSetAttribute(kMain, cudaFuncAttributeMaxDynamicSharedMemorySize,
                             SMEM_BYTES);
        attr_done = true;
    }

    kMain<<<NBLK, NT, SMEM_BYTES>>>(logits, reg, props, feats, out);
}